// round 2
// baseline (speedup 1.0000x reference)
#include <cuda_runtime.h>
#include <math.h>

#define N_NODES 50000
#define N_EDGES 800000
#define N_TOT   (N_EDGES + N_NODES)   // edges + self loops
#define IN_DIM  128
#define HIDDEN  64
#define NEG_SLOPE 0.2f

// ---------------- scratch (__device__ globals; no allocations) ----------------
__device__ float4 g_h4[N_NODES * (HIDDEN / 4)];         // h [N, 64] as float4
__device__ float  g_asrc[N_NODES];
__device__ float  g_adst[N_NODES];
__device__ int    g_cnt[N_NODES];
__device__ int    g_row_start[N_NODES + 1];
__device__ int    g_cursor[N_NODES];
__device__ int    g_csr_src[N_TOT];
__device__ float  g_csr_e[N_TOT];
__device__ int    g_is64;

// ---------------- K0: detect edge_index dtype (int32 vs int64) ----------------
// If data is int64 with values in [0, N_NODES), all 8-byte reads are in range.
// If data is int32, the 8-byte view combines two random int32s -> huge values.
__global__ void k_detect(const void* __restrict__ ei_raw) {
    if (threadIdx.x != 0 || blockIdx.x != 0) return;
    const long long* p = (const long long*)ei_raw;
    int ok64 = 1;
    for (int i = 0; i < 256; i++) {
        long long v = p[i];
        if (v < 0 || v >= N_NODES) { ok64 = 0; break; }
    }
    g_is64 = ok64;
}

__device__ __forceinline__ int load_idx(const void* ei_raw, int pos, int is64) {
    if (is64) return (int)((const long long*)ei_raw)[pos];
    return ((const int*)ei_raw)[pos];
}

// ---------------- K1: h = x @ W^T  (fp32 tiled smem GEMM) ----------------
#define TN 32
__global__ __launch_bounds__(256) void k_gemm(const float* __restrict__ x,
                                              const float* __restrict__ W) {
    __shared__ float Xs[TN][IN_DIM];       // 16KB
    __shared__ float Wt[IN_DIM][HIDDEN];   // 32KB (W transposed: Wt[c][k])
    const int tid = threadIdx.x;
    const int n0  = blockIdx.x * TN;

    for (int i = tid; i < HIDDEN * IN_DIM; i += 256) {
        int k = i >> 7, c = i & 127;
        Wt[c][k] = W[i];
    }
    const float4* x4 = (const float4*)x;
    for (int i = tid; i < TN * (IN_DIM / 4); i += 256) {
        int n = i >> 5;
        int c4 = i & 31;
        int node = n0 + n;
        float4 v = (node < N_NODES) ? x4[(size_t)node * 32 + c4]
                                    : make_float4(0.f, 0.f, 0.f, 0.f);
        ((float4*)Xs[n])[c4] = v;
    }
    __syncthreads();

    const int tx = tid & 15;   // k quad
    const int ty = tid >> 4;   // node pair
    float acc[2][4] = {{0.f,0.f,0.f,0.f},{0.f,0.f,0.f,0.f}};

#pragma unroll 4
    for (int c = 0; c < IN_DIM; c++) {
        float4 wv = *(const float4*)&Wt[c][tx * 4];
        float xa = Xs[ty * 2 + 0][c];
        float xb = Xs[ty * 2 + 1][c];
        acc[0][0] += xa * wv.x; acc[0][1] += xa * wv.y;
        acc[0][2] += xa * wv.z; acc[0][3] += xa * wv.w;
        acc[1][0] += xb * wv.x; acc[1][1] += xb * wv.y;
        acc[1][2] += xb * wv.z; acc[1][3] += xb * wv.w;
    }

    float* hptr = (float*)g_h4;
#pragma unroll
    for (int i = 0; i < 2; i++) {
        int node = n0 + ty * 2 + i;
        if (node < N_NODES) {
            float4 v = make_float4(acc[i][0], acc[i][1], acc[i][2], acc[i][3]);
            *(float4*)&hptr[(size_t)node * HIDDEN + tx * 4] = v;
        }
    }
}

// ---------------- K2: a_src / a_dst (warp per node) ----------------
__global__ __launch_bounds__(256) void k_att(const float* __restrict__ att_src,
                                             const float* __restrict__ att_dst) {
    int node = blockIdx.x * 8 + (threadIdx.x >> 5);
    int lane = threadIdx.x & 31;
    if (node >= N_NODES) return;
    const float2* h2 = (const float2*)g_h4;
    float2 hv = h2[(size_t)node * 32 + lane];
    float s1 = hv.x * att_src[2 * lane] + hv.y * att_src[2 * lane + 1];
    float s2 = hv.x * att_dst[2 * lane] + hv.y * att_dst[2 * lane + 1];
#pragma unroll
    for (int off = 16; off > 0; off >>= 1) {
        s1 += __shfl_xor_sync(0xffffffffu, s1, off);
        s2 += __shfl_xor_sync(0xffffffffu, s2, off);
    }
    if (lane == 0) { g_asrc[node] = s1; g_adst[node] = s2; }
}

// ---------------- K3: init counts (self loop => start at 1) ----------------
__global__ void k_init_cnt() {
    int i = blockIdx.x * 256 + threadIdx.x;
    if (i < N_NODES) g_cnt[i] = 1;
}

// ---------------- K4: degree count over real edges ----------------
__global__ void k_count(const void* __restrict__ ei) {
    int e = blockIdx.x * 256 + threadIdx.x;
    if (e < N_EDGES) {
        int is64 = g_is64;
        int dst = load_idx(ei, N_EDGES + e, is64);
        atomicAdd(&g_cnt[dst], 1);
    }
}

// ---------------- K5: single-block exclusive scan ----------------
__global__ __launch_bounds__(1024) void k_scan() {
    __shared__ int warp_off[32];
    __shared__ int carry_sh;
    if (threadIdx.x == 0) carry_sh = 0;
    __syncthreads();
    int lane = threadIdx.x & 31;
    int wid  = threadIdx.x >> 5;
    for (int base = 0; base < N_NODES; base += 1024) {
        int i = base + (int)threadIdx.x;
        int v = (i < N_NODES) ? g_cnt[i] : 0;
        int incl = v;
#pragma unroll
        for (int off = 1; off < 32; off <<= 1) {
            int t = __shfl_up_sync(0xffffffffu, incl, off);
            if (lane >= off) incl += t;
        }
        if (lane == 31) warp_off[wid] = incl;
        __syncthreads();
        if (threadIdx.x < 32) {
            int ws = warp_off[threadIdx.x];
            int wincl = ws;
#pragma unroll
            for (int off = 1; off < 32; off <<= 1) {
                int t = __shfl_up_sync(0xffffffffu, wincl, off);
                if (lane >= off) wincl += t;
            }
            warp_off[threadIdx.x] = wincl - ws;
        }
        __syncthreads();
        int carry = carry_sh;
        int excl = carry + warp_off[wid] + incl - v;
        if (i < N_NODES) {
            g_row_start[i] = excl;
            g_cursor[i]    = excl;
        }
        __syncthreads();
        if (threadIdx.x == 1023) carry_sh = excl + v;
        __syncthreads();
    }
    if (threadIdx.x == 0) g_row_start[N_NODES] = carry_sh;
}

// ---------------- K6: scatter edges into CSR (+ precompute logits) ----------------
__global__ void k_scatter(const void* __restrict__ ei) {
    int e = blockIdx.x * 256 + threadIdx.x;
    if (e >= N_TOT) return;
    int src, dst;
    if (e < N_EDGES) {
        int is64 = g_is64;
        src = load_idx(ei, e, is64);
        dst = load_idx(ei, N_EDGES + e, is64);
    } else {
        src = dst = e - N_EDGES;   // self loop
    }
    float v = g_asrc[src] + g_adst[dst];
    float ev = (v > 0.f) ? v : NEG_SLOPE * v;
    int pos = atomicAdd(&g_cursor[dst], 1);
    g_csr_src[pos] = src;
    g_csr_e[pos]   = ev;
}

// ---------------- K7: fused softmax + aggregate + head (warp per node) ----------------
__global__ __launch_bounds__(256) void k_agg(const float* __restrict__ bias,
                                             const float* __restrict__ wlin,
                                             const float* __restrict__ blin,
                                             float* __restrict__ y) {
    int node = blockIdx.x * 8 + (threadIdx.x >> 5);
    int lane = threadIdx.x & 31;
    if (node >= N_NODES) return;

    int beg = g_row_start[node];
    int end = g_row_start[node + 1];

    float m = -INFINITY;
    for (int i = beg + lane; i < end; i += 32) m = fmaxf(m, g_csr_e[i]);
#pragma unroll
    for (int off = 16; off > 0; off >>= 1)
        m = fmaxf(m, __shfl_xor_sync(0xffffffffu, m, off));

    const float2* h2 = (const float2*)g_h4;
    float2 acc = make_float2(0.f, 0.f);
    float s = 0.f;
    for (int base = beg; base < end; base += 32) {
        int i = base + lane;
        float ex = 0.f;
        int sid = 0;
        if (i < end) {
            ex = expf(g_csr_e[i] - m);
            sid = g_csr_src[i];
        }
        s += ex;
        int cnt = min(32, end - base);
        for (int j = 0; j < cnt; j++) {
            float w = __shfl_sync(0xffffffffu, ex, j);
            int sj  = __shfl_sync(0xffffffffu, sid, j);
            if (w != 0.f) {
                float2 hv = h2[(size_t)sj * 32 + lane];
                acc.x += w * hv.x;
                acc.y += w * hv.y;
            }
        }
    }
#pragma unroll
    for (int off = 16; off > 0; off >>= 1)
        s += __shfl_xor_sync(0xffffffffu, s, off);

    float inv = 1.f / s;
    float o0 = fmaxf(acc.x * inv + bias[2 * lane], 0.f);
    float o1 = fmaxf(acc.y * inv + bias[2 * lane + 1], 0.f);
    float p = o0 * wlin[2 * lane] + o1 * wlin[2 * lane + 1];
#pragma unroll
    for (int off = 16; off > 0; off >>= 1)
        p += __shfl_xor_sync(0xffffffffu, p, off);
    if (lane == 0) {
        float t = p + blin[0];
        y[node] = 1.f / (1.f + expf(-t));
    }
}

// ---------------- launch ----------------
extern "C" void kernel_launch(void* const* d_in, const int* in_sizes, int n_in,
                              void* d_out, int out_size) {
    const float* x       = (const float*)d_in[0];
    const void*  ei      = d_in[1];
    const float* W       = (const float*)d_in[2];
    const float* att_src = (const float*)d_in[3];
    const float* att_dst = (const float*)d_in[4];
    const float* bias    = (const float*)d_in[5];
    const float* wlin    = (const float*)d_in[6];
    const float* blin    = (const float*)d_in[7];
    float*       y       = (float*)d_out;

    k_detect<<<1, 32>>>(ei);
    k_gemm<<<(N_NODES + TN - 1) / TN, 256>>>(x, W);
    k_att<<<(N_NODES + 7) / 8, 256>>>(att_src, att_dst);
    k_init_cnt<<<(N_NODES + 255) / 256, 256>>>();
    k_count<<<(N_EDGES + 255) / 256, 256>>>(ei);
    k_scan<<<1, 1024>>>();
    k_scatter<<<(N_TOT + 255) / 256, 256>>>(ei);
    k_agg<<<(N_NODES + 7) / 8, 256>>>(bias, wlin, blin, y);
}

// round 3
// speedup vs baseline: 1.4917x; 1.4917x over previous
#include <cuda_runtime.h>
#include <math.h>

#define N_NODES 50000
#define N_EDGES 800000
#define N_TOT   (N_EDGES + N_NODES)   // edges + self loops
#define IN_DIM  128
#define HIDDEN  64
#define NEG_SLOPE 0.2f

// ---------------- scratch (__device__ globals; no allocations) ----------------
__device__ __align__(16) float g_h[N_NODES * HIDDEN];      // h [N, 64]
__device__ float  g_asrc[N_NODES];
__device__ float  g_adst[N_NODES];
__device__ __align__(16) int g_cnt[N_NODES];
__device__ __align__(16) int g_row_start[N_NODES + 4];
__device__ __align__(16) int g_cursor[N_NODES];
__device__ __align__(16) int g_csr_src[N_TOT];
__device__ __align__(16) float g_csr_e[N_TOT];
__device__ int    g_is64;

// ---------------- packed fp32x2 helpers ----------------
__device__ __forceinline__ void ffma2(unsigned long long& acc,
                                      unsigned long long a,
                                      unsigned long long b) {
    asm("fma.rn.f32x2 %0, %1, %2, %0;" : "+l"(acc) : "l"(a), "l"(b));
}
__device__ __forceinline__ unsigned long long pack2(float lo, float hi) {
    unsigned long long r;
    asm("mov.b64 %0, {%1, %2};" : "=l"(r) : "f"(lo), "f"(hi));
    return r;
}
__device__ __forceinline__ void unpack2(unsigned long long v, float& lo, float& hi) {
    asm("mov.b64 {%0, %1}, %2;" : "=f"(lo), "=f"(hi) : "l"(v));
}

// ---------------- K0: init counts + dtype detect (parallel) ----------------
__global__ void k_init(const void* __restrict__ ei_raw) {
    int i = blockIdx.x * 256 + threadIdx.x;
    if (i < N_NODES) g_cnt[i] = 1;            // self loop contributes 1
    if (i == 0) g_row_start[N_NODES] = N_TOT; // constant total
    if (blockIdx.x == 0 && threadIdx.x < 32) {
        // If data were int64 with valid ids, all 8-byte reads land in range.
        const long long* p = (const long long*)ei_raw;
        int bad = 0;
#pragma unroll
        for (int j = 0; j < 8; j++) {
            long long v = p[threadIdx.x * 8 + j];
            if (v < 0 || v >= N_NODES) bad = 1;
        }
        unsigned any = __ballot_sync(0xffffffffu, bad);
        if (threadIdx.x == 0) g_is64 = (any == 0u) ? 1 : 0;
    }
}

// ---------------- K1: h = x @ W^T (fp32x2 packed GEMM) + fused a_src/a_dst ----
#define GN 64   // nodes per block
__global__ __launch_bounds__(256) void k_gemm(const float* __restrict__ x,
                                              const float* __restrict__ W,
                                              const float* __restrict__ att_src,
                                              const float* __restrict__ att_dst) {
    __shared__ float Wt[IN_DIM][HIDDEN];   // 32KB, Wt[c][k]
    __shared__ float Xs[GN][64];           // 16KB, one 64-col chunk
    const int tid = threadIdx.x;
    const int n0  = blockIdx.x * GN;

    for (int i = tid; i < HIDDEN * IN_DIM; i += 256) {
        int k = i >> 7, c = i & 127;
        Wt[c][k] = W[i];
    }

    const int tx = tid & 15;   // k quad: k = tx*4 .. tx*4+3
    const int ty = tid >> 4;   // node group: nodes n0 + ty*4 .. +3
    unsigned long long acc[4][2];
#pragma unroll
    for (int n = 0; n < 4; n++) { acc[n][0] = 0ull; acc[n][1] = 0ull; }

    const float4* x4 = (const float4*)x;
    for (int kc = 0; kc < 2; kc++) {
        __syncthreads();   // Wt ready / Xs no longer in use
        for (int i = tid; i < GN * 16; i += 256) {
            int n = i >> 4, c4 = i & 15;
            int node = n0 + n;
            float4 v = (node < N_NODES) ? x4[(size_t)node * 32 + kc * 16 + c4]
                                        : make_float4(0.f, 0.f, 0.f, 0.f);
            ((float4*)Xs[n])[c4] = v;
        }
        __syncthreads();
#pragma unroll 8
        for (int c = 0; c < 64; c++) {
            ulonglong2 wp = *(const ulonglong2*)&Wt[kc * 64 + c][tx * 4];
#pragma unroll
            for (int n = 0; n < 4; n++) {
                float xv = Xs[ty * 4 + n][c];
                unsigned long long xx = pack2(xv, xv);
                ffma2(acc[n][0], xx, wp.x);
                ffma2(acc[n][1], xx, wp.y);
            }
        }
    }

    // epilogue: store h + fused attention coefficients
    float4 as4 = ((const float4*)att_src)[tx];
    float4 ad4 = ((const float4*)att_dst)[tx];
#pragma unroll
    for (int n = 0; n < 4; n++) {
        float h0, h1, h2, h3;
        unpack2(acc[n][0], h0, h1);
        unpack2(acc[n][1], h2, h3);
        int node = n0 + ty * 4 + n;
        if (node < N_NODES) {
            *(float4*)&g_h[(size_t)node * HIDDEN + tx * 4] =
                make_float4(h0, h1, h2, h3);
        }
        float s1 = h0 * as4.x + h1 * as4.y + h2 * as4.z + h3 * as4.w;
        float s2 = h0 * ad4.x + h1 * ad4.y + h2 * ad4.z + h3 * ad4.w;
#pragma unroll
        for (int off = 8; off > 0; off >>= 1) {
            s1 += __shfl_xor_sync(0xffffffffu, s1, off);
            s2 += __shfl_xor_sync(0xffffffffu, s2, off);
        }
        if (tx == 0 && node < N_NODES) {
            g_asrc[node] = s1;
            g_adst[node] = s2;
        }
    }
}

// ---------------- K2: degree count (4 edges / thread) ----------------
__global__ void k_count(const void* __restrict__ ei) {
    int t = blockIdx.x * 256 + threadIdx.x;
    if (t >= N_EDGES / 4) return;
    if (g_is64) {
        const long long* p = (const long long*)ei + N_EDGES + (size_t)t * 4;
#pragma unroll
        for (int j = 0; j < 4; j++) atomicAdd(&g_cnt[(int)p[j]], 1);
    } else {
        int4 d = ((const int4*)ei)[N_EDGES / 4 + t];
        atomicAdd(&g_cnt[d.x], 1);
        atomicAdd(&g_cnt[d.y], 1);
        atomicAdd(&g_cnt[d.z], 1);
        atomicAdd(&g_cnt[d.w], 1);
    }
}

// ---------------- K3: single-block exclusive scan (int4 vectorized) ----------
#define SCAN_N4 (N_NODES / 4)   // 12500
__global__ __launch_bounds__(1024) void k_scan() {
    __shared__ int warp_off[32];
    __shared__ int carry_sh;
    if (threadIdx.x == 0) carry_sh = 0;
    __syncthreads();
    int lane = threadIdx.x & 31;
    int wid  = threadIdx.x >> 5;
    for (int base = 0; base < SCAN_N4; base += 1024) {
        int i = base + (int)threadIdx.x;
        bool valid = (i < SCAN_N4);
        int4 v = valid ? ((const int4*)g_cnt)[i] : make_int4(0, 0, 0, 0);
        int s = v.x + v.y + v.z + v.w;
        int incl = s;
#pragma unroll
        for (int off = 1; off < 32; off <<= 1) {
            int t = __shfl_up_sync(0xffffffffu, incl, off);
            if (lane >= off) incl += t;
        }
        if (lane == 31) warp_off[wid] = incl;
        __syncthreads();
        if (threadIdx.x < 32) {
            int ws = warp_off[threadIdx.x];
            int wincl = ws;
#pragma unroll
            for (int off = 1; off < 32; off <<= 1) {
                int t = __shfl_up_sync(0xffffffffu, wincl, off);
                if (lane >= off) wincl += t;
            }
            warp_off[threadIdx.x] = wincl - ws;
        }
        __syncthreads();
        int carry = carry_sh;
        int excl = carry + warp_off[wid] + incl - s;
        if (valid) {
            int e0 = excl, e1 = e0 + v.x, e2 = e1 + v.y, e3 = e2 + v.z;
            int4 r = make_int4(e0, e1, e2, e3);
            ((int4*)g_row_start)[i] = r;
            ((int4*)g_cursor)[i]    = r;
        }
        __syncthreads();
        if (threadIdx.x == 1023) carry_sh = excl + s;
        __syncthreads();
    }
}

// ---------------- K4: scatter edges + self loops into CSR ----------------
__global__ void k_scatter(const void* __restrict__ ei) {
    int t = blockIdx.x * 256 + threadIdx.x;
    if (t < N_EDGES / 4) {
        int sx[4], dx[4];
        if (g_is64) {
            const long long* ps = (const long long*)ei + (size_t)t * 4;
            const long long* pd = ps + N_EDGES;
#pragma unroll
            for (int j = 0; j < 4; j++) { sx[j] = (int)ps[j]; dx[j] = (int)pd[j]; }
        } else {
            int4 s4 = ((const int4*)ei)[t];
            int4 d4 = ((const int4*)ei)[N_EDGES / 4 + t];
            sx[0] = s4.x; sx[1] = s4.y; sx[2] = s4.z; sx[3] = s4.w;
            dx[0] = d4.x; dx[1] = d4.y; dx[2] = d4.z; dx[3] = d4.w;
        }
#pragma unroll
        for (int j = 0; j < 4; j++) {
            float v = g_asrc[sx[j]] + g_adst[dx[j]];
            float ev = (v > 0.f) ? v : NEG_SLOPE * v;
            int pos = atomicAdd(&g_cursor[dx[j]], 1);
            g_csr_src[pos] = sx[j];
            g_csr_e[pos]   = ev;
        }
    } else {
        int node = t - N_EDGES / 4;   // self loop
        if (node < N_NODES) {
            float v = g_asrc[node] + g_adst[node];
            float ev = (v > 0.f) ? v : NEG_SLOPE * v;
            int pos = atomicAdd(&g_cursor[node], 1);
            g_csr_src[pos] = node;
            g_csr_e[pos]   = ev;
        }
    }
}

// ---------------- K5: fused softmax + aggregate + head (warp per node) -------
__global__ __launch_bounds__(256) void k_agg(const float* __restrict__ bias,
                                             const float* __restrict__ wlin,
                                             const float* __restrict__ blin,
                                             float* __restrict__ y) {
    int node = blockIdx.x * 8 + (threadIdx.x >> 5);
    int lane = threadIdx.x & 31;
    if (node >= N_NODES) return;

    int beg = g_row_start[node];
    int end = g_row_start[node + 1];

    float m = -INFINITY;
    for (int i = beg + lane; i < end; i += 32) m = fmaxf(m, g_csr_e[i]);
#pragma unroll
    for (int off = 16; off > 0; off >>= 1)
        m = fmaxf(m, __shfl_xor_sync(0xffffffffu, m, off));

    const float2* h2 = (const float2*)g_h;
    float2 acc = make_float2(0.f, 0.f);
    float s = 0.f;
    for (int base = beg; base < end; base += 32) {
        int i = base + lane;
        float ex = 0.f;
        int sid = 0;
        if (i < end) {
            ex = __expf(g_csr_e[i] - m);
            sid = g_csr_src[i];
        }
        s += ex;
        int cnt = min(32, end - base);
        for (int j = 0; j < cnt; j++) {
            float w = __shfl_sync(0xffffffffu, ex, j);
            int sj  = __shfl_sync(0xffffffffu, sid, j);
            float2 hv = h2[(size_t)sj * 32 + lane];
            acc.x += w * hv.x;
            acc.y += w * hv.y;
        }
    }
#pragma unroll
    for (int off = 16; off > 0; off >>= 1)
        s += __shfl_xor_sync(0xffffffffu, s, off);

    float inv = __frcp_rn(s);
    float o0 = fmaxf(acc.x * inv + bias[2 * lane], 0.f);
    float o1 = fmaxf(acc.y * inv + bias[2 * lane + 1], 0.f);
    float p = o0 * wlin[2 * lane] + o1 * wlin[2 * lane + 1];
#pragma unroll
    for (int off = 16; off > 0; off >>= 1)
        p += __shfl_xor_sync(0xffffffffu, p, off);
    if (lane == 0) {
        float t = p + blin[0];
        y[node] = __frcp_rn(1.f + __expf(-t));
    }
}

// ---------------- launch ----------------
extern "C" void kernel_launch(void* const* d_in, const int* in_sizes, int n_in,
                              void* d_out, int out_size) {
    const float* x       = (const float*)d_in[0];
    const void*  ei      = d_in[1];
    const float* W       = (const float*)d_in[2];
    const float* att_src = (const float*)d_in[3];
    const float* att_dst = (const float*)d_in[4];
    const float* bias    = (const float*)d_in[5];
    const float* wlin    = (const float*)d_in[6];
    const float* blin    = (const float*)d_in[7];
    float*       y       = (float*)d_out;

    k_init<<<(N_NODES + 255) / 256, 256>>>(ei);
    k_gemm<<<(N_NODES + GN - 1) / GN, 256>>>(x, W, att_src, att_dst);
    k_count<<<(N_EDGES / 4 + 255) / 256, 256>>>(ei);
    k_scan<<<1, 1024>>>();
    k_scatter<<<(N_EDGES / 4 + N_NODES + 255) / 256, 256>>>(ei);
    k_agg<<<(N_NODES + 7) / 8, 256>>>(bias, wlin, blin, y);
}